// round 12
// baseline (speedup 1.0000x reference)
#include <cuda_runtime.h>
#include <math.h>
#include <stdint.h>

#define TAU_INV (1.0f / 0.07f)
#define Nn 8192
#define Dd 256
#define JYS 64                  // column jobs per jx (128 cols each)
#define JXN 64                  // row tiles (128 rows each)
#define NJOB (JXN * JYS)        // 4096
#define QINV (1.0 / 16129.0)    // 1/127^2
#define K2C ((float)((1.0/0.07) * QINV * 1.4426950408889634))
#define C2C ((float)((1.0/0.07) * 1.4426950408889634))

// ---- scratch (__device__ globals; allocation-free contract) ----
__device__ uint32_t g_Aq[(size_t)Nn * 64];   // int8x4, word-swizzled rows
__device__ uint32_t g_Bq[(size_t)Nn * 64];
__device__ float g_diag[Nn];
__device__ float g_s[(size_t)JYS * Nn];      // [jy][row]
__device__ float g_part[32];
__device__ int g_ctr;                        // job queue (self-resetting)
__device__ int g_fin;                        // finalize ticket (self-resetting)

// smem byte offsets (single dynamic allocation)
#define SO_A0   0
#define SO_A1   32768
#define SO_B0   65536            // 16KB (64 cols x 256B)
#define SO_B1   81920
#define SO_LBL  98304            // 2 x 128 ints
#define SO_ROW  99328            // 128 x 4 floats
#define SO_JOB  101376
#define SMEM_TOT 101440

// ---------------------------------------------------------------------------
// Kernel 1: fused norms + diag + int8 quantize (row stays in registers).
// One warp per row. Butterfly allreduce puts sums in every lane.
// Swizzled word layout p = j ^ (4*(row&7)) -> conflict-free IMMA LDS.
// ---------------------------------------------------------------------------
__global__ void norm_convert_kernel(const float* __restrict__ im,
                                    const float* __restrict__ rec) {
    int row = (blockIdx.x * blockDim.x + threadIdx.x) >> 5;
    int lane = threadIdx.x & 31;
    const float4* a4 = (const float4*)(im + (size_t)row * Dd);
    const float4* b4 = (const float4*)(rec + (size_t)row * Dd);
    float4 xa0 = a4[lane], xa1 = a4[lane + 32];
    float4 xb0 = b4[lane], xb1 = b4[lane + 32];

    float ssi = xa0.x*xa0.x + xa0.y*xa0.y + xa0.z*xa0.z + xa0.w*xa0.w
              + xa1.x*xa1.x + xa1.y*xa1.y + xa1.z*xa1.z + xa1.w*xa1.w;
    float ssr = xb0.x*xb0.x + xb0.y*xb0.y + xb0.z*xb0.z + xb0.w*xb0.w
              + xb1.x*xb1.x + xb1.y*xb1.y + xb1.z*xb1.z + xb1.w*xb1.w;
    float dot = xa0.x*xb0.x + xa0.y*xb0.y + xa0.z*xb0.z + xa0.w*xb0.w
              + xa1.x*xb1.x + xa1.y*xb1.y + xa1.z*xb1.z + xa1.w*xb1.w;
#pragma unroll
    for (int o = 16; o > 0; o >>= 1) {
        ssi += __shfl_xor_sync(0xffffffffu, ssi, o);
        ssr += __shfl_xor_sync(0xffffffffu, ssr, o);
        dot += __shfl_xor_sync(0xffffffffu, dot, o);
    }
    float ii = 1.0f / fmaxf(sqrtf(ssi), 1e-6f);
    float ir = 1.0f / fmaxf(sqrtf(ssr), 1e-6f);
    if (lane == 0) g_diag[row] = dot * ii * ir * TAU_INV;

    float fa = ii * 127.f, fb = ir * 127.f;
    int p0 = lane ^ (4 * (row & 7));
    int p1 = (lane + 32) ^ (4 * (row & 7));
    int q0, q1, q2, q3;
    q0 = __float2int_rn(xa0.x * fa); q1 = __float2int_rn(xa0.y * fa);
    q2 = __float2int_rn(xa0.z * fa); q3 = __float2int_rn(xa0.w * fa);
    g_Aq[row * 64 + p0] = (q0 & 0xFF) | ((q1 & 0xFF) << 8) | ((q2 & 0xFF) << 16) | (q3 << 24);
    q0 = __float2int_rn(xa1.x * fa); q1 = __float2int_rn(xa1.y * fa);
    q2 = __float2int_rn(xa1.z * fa); q3 = __float2int_rn(xa1.w * fa);
    g_Aq[row * 64 + p1] = (q0 & 0xFF) | ((q1 & 0xFF) << 8) | ((q2 & 0xFF) << 16) | (q3 << 24);
    q0 = __float2int_rn(xb0.x * fb); q1 = __float2int_rn(xb0.y * fb);
    q2 = __float2int_rn(xb0.z * fb); q3 = __float2int_rn(xb0.w * fb);
    g_Bq[row * 64 + p0] = (q0 & 0xFF) | ((q1 & 0xFF) << 8) | ((q2 & 0xFF) << 16) | (q3 << 24);
    q0 = __float2int_rn(xb1.x * fb); q1 = __float2int_rn(xb1.y * fb);
    q2 = __float2int_rn(xb1.z * fb); q3 = __float2int_rn(xb1.w * fb);
    g_Bq[row * 64 + p1] = (q0 & 0xFF) | ((q1 & 0xFF) << 8) | ((q2 & 0xFF) << 16) | (q3 << 24);
}

// ---------------------------------------------------------------------------
// Kernel 2: persistent int8 IMMA GEMM, 128x128 jobs (small tail quantum),
// early job grab + cross-job A/B prefetch, pipelined exp-sum epilogue.
// ---------------------------------------------------------------------------
#define IMMA(c, av, bv) \
    asm volatile("mma.sync.aligned.m16n8k32.row.col.s32.s8.s8.s32 " \
                 "{%0,%1,%2,%3},{%4,%5,%6,%7},{%8,%9},{%0,%1,%2,%3};" \
                 : "+r"((c)[0]), "+r"((c)[1]), "+r"((c)[2]), "+r"((c)[3]) \
                 : "r"((av)[0]), "r"((av)[1]), "r"((av)[2]), "r"((av)[3]), \
                   "r"((bv)[0]), "r"((bv)[1]))
#define WAIT0() asm volatile("cp.async.wait_group 0;")

__device__ __forceinline__ float ex2f(float x) {
    float r;
    asm("ex2.approx.ftz.f32 %0, %1;" : "=f"(r) : "f"(x));
    return r;
}

__device__ __forceinline__ void copyA(char* dst, int rb, int tid) {
#pragma unroll
    for (int i = 0; i < 8; i++) {
        int id = tid + i * 256;
        int row = id >> 4, c = (id & 15) * 16;
        uint32_t d = (uint32_t)__cvta_generic_to_shared(dst + row * 256 + c);
        const char* s = (const char*)g_Aq + (size_t)(rb + row) * 256 + c;
        asm volatile("cp.async.cg.shared.global [%0], [%1], 16;" :: "r"(d), "l"(s));
    }
    asm volatile("cp.async.commit_group;");
}
__device__ __forceinline__ void copyB(char* dst, int jb, int tid) {
#pragma unroll
    for (int i = 0; i < 4; i++) {
        int id = tid + i * 256;
        int row = id >> 4, c = (id & 15) * 16;
        uint32_t d = (uint32_t)__cvta_generic_to_shared(dst + row * 256 + c);
        const char* s = (const char*)g_Bq + (size_t)(jb + row) * 256 + c;
        asm volatile("cp.async.cg.shared.global [%0], [%1], 16;" :: "r"(d), "l"(s));
    }
    asm volatile("cp.async.commit_group;");
}

__device__ __forceinline__ void mma_tile(int acc[4][2][4], const uint32_t* Aw,
                                         const uint32_t* Bw, int warp_m,
                                         int warp_n, int qr, int qc) {
#pragma unroll
    for (int mi = 0; mi < 4; mi++)
#pragma unroll
        for (int ni = 0; ni < 2; ni++)
#pragma unroll
            for (int k = 0; k < 4; k++) acc[mi][ni][k] = 0;
    int swz = 4 * qr;
#pragma unroll
    for (int ks = 0; ks < 8; ks++) {
        int w0 = (8 * ks + qc) ^ swz;
        int w1 = (8 * ks + 4 + qc) ^ swz;
        uint32_t a[4][4];
#pragma unroll
        for (int mi = 0; mi < 4; mi++) {
            int r0 = (warp_m * 64 + mi * 16 + qr) * 64;
            a[mi][0] = Aw[r0 + w0];
            a[mi][1] = Aw[r0 + 512 + w0];
            a[mi][2] = Aw[r0 + w1];
            a[mi][3] = Aw[r0 + 512 + w1];
        }
        uint32_t b[2][2];
#pragma unroll
        for (int ni = 0; ni < 2; ni++) {
            int rn = (warp_n * 16 + ni * 8 + qr) * 64;
            b[ni][0] = Bw[rn + w0];
            b[ni][1] = Bw[rn + w1];
        }
#pragma unroll
        for (int mi = 0; mi < 4; mi++)
#pragma unroll
            for (int ni = 0; ni < 2; ni++)
                IMMA(acc[mi][ni], a[mi], b[ni]);
    }
}

__device__ __forceinline__ void epi_tile(const int acc[4][2][4], int t, int rb,
                                         int jb0, const int* lblS,
                                         const int labR[4][2], float s[4][2],
                                         int warp_m, int warp_n, int qr, int qc) {
    int jb = jb0 + t * 64;
#pragma unroll
    for (int mi = 0; mi < 4; mi++) {
        int gi0 = rb + warp_m * 64 + mi * 16 + qr;
        int gi1 = gi0 + 8;
#pragma unroll
        for (int ni = 0; ni < 2; ni++) {
            int cl0 = warp_n * 16 + ni * 8 + 2 * qc;
            int cl1 = cl0 + 1;
            int lb0 = lblS[t * 64 + cl0], lb1 = lblS[t * 64 + cl1];
            int gj0 = jb + cl0, gj1 = jb + cl1;
            float e0 = ex2f(fmaf((float)acc[mi][ni][0], K2C, -C2C));
            float e1 = ex2f(fmaf((float)acc[mi][ni][1], K2C, -C2C));
            float e2 = ex2f(fmaf((float)acc[mi][ni][2], K2C, -C2C));
            float e3 = ex2f(fmaf((float)acc[mi][ni][3], K2C, -C2C));
            s[mi][0] += (labR[mi][0] != lb0 || gi0 == gj0) ? e0 : 0.f;
            s[mi][0] += (labR[mi][0] != lb1 || gi0 == gj1) ? e1 : 0.f;
            s[mi][1] += (labR[mi][1] != lb0 || gi1 == gj0) ? e2 : 0.f;
            s[mi][1] += (labR[mi][1] != lb1 || gi1 == gj1) ? e3 : 0.f;
        }
    }
}

__global__ void __launch_bounds__(256, 2)
gemm_lse_imma(const int* __restrict__ labels, int n) {
    extern __shared__ __align__(16) char dsm[];
    char* Abuf[2] = {dsm + SO_A0, dsm + SO_A1};
    char* B0 = dsm + SO_B0;
    char* B1 = dsm + SO_B1;
    int* lbl = (int*)(dsm + SO_LBL);                 // [2][128]
    float (*rowsum)[4] = (float (*)[4])(dsm + SO_ROW);
    int* jobs = (int*)(dsm + SO_JOB);

    int tid = threadIdx.x, lane = tid & 31, wid = tid >> 5;
    int warp_m = wid >> 2, warp_n = wid & 3;
    int qr = lane >> 2, qc = lane & 3;

    int accA[4][2][4], accB[4][2][4];

    if (tid == 0) jobs[0] = atomicAdd(&g_ctr, 1);
    __syncthreads();
    int job = jobs[0];
    int cnt = 1, p = 0, acur = 0;
    int jx = job >> 6;
    if (job < NJOB) {
        int rb = jx * 128, jb0 = (job & 63) * 128;
        copyA(Abuf[0], rb, tid);
        copyB(B0, jb0, tid);
        if (tid < 128) lbl[tid] = labels[jb0 + tid];
    }

    while (job < NJOB) {
        int jy = job & 63;
        int rb = jx * 128, jb0 = jy * 128;
        const uint32_t* Aw = (const uint32_t*)Abuf[acur];
        const int* lblS = lbl + p * 128;

        int labR[4][2];
#pragma unroll
        for (int mi = 0; mi < 4; mi++) {
            int r = rb + warp_m * 64 + mi * 16 + qr;
            labR[mi][0] = labels[r];
            labR[mi][1] = labels[r + 8];
        }
        float s[4][2] = {{0.f,0.f},{0.f,0.f},{0.f,0.f},{0.f,0.f}};

        // ---- t0: (A, B0 ready) issue B1, early-grab next job, mma accA
        WAIT0();
        __syncthreads();
        copyB(B1, jb0 + 64, tid);
        if (tid == 0) jobs[1] = atomicAdd(&g_ctr, 1);
        mma_tile(accA, Aw, (const uint32_t*)B0, warp_m, warp_n, qr, qc);
        // ---- t1: (B1 ready, jobs[1] visible) prefetch next job, mma accB
        WAIT0();
        __syncthreads();
        int nj = jobs[1];
        cnt++;
        int njx = nj >> 6;
        int aflip = 0;
        if (nj < NJOB) {
            if (njx != jx) { copyA(Abuf[acur ^ 1], njx * 128, tid); aflip = 1; }
            copyB(B0, (nj & 63) * 128, tid);
            if (tid < 128) lbl[(p ^ 1) * 128 + tid] = labels[(nj & 63) * 128 + tid];
        }
        mma_tile(accB, Aw, (const uint32_t*)B1, warp_m, warp_n, qr, qc);
        epi_tile(accA, 0, rb, jb0, lblS, labR, s, warp_m, warp_n, qr, qc);
        epi_tile(accB, 1, rb, jb0, lblS, labR, s, warp_m, warp_n, qr, qc);

        // ---- flush: qc-quad reduce, per-(row,warp_n) smem slots, row sum
#pragma unroll
        for (int mi = 0; mi < 4; mi++)
#pragma unroll
            for (int h = 0; h < 2; h++) {
                s[mi][h] += __shfl_xor_sync(0xffffffffu, s[mi][h], 1);
                s[mi][h] += __shfl_xor_sync(0xffffffffu, s[mi][h], 2);
            }
        if (qc == 0) {
#pragma unroll
            for (int mi = 0; mi < 4; mi++) {
                int r0 = warp_m * 64 + mi * 16 + qr;
                rowsum[r0][warp_n] = s[mi][0];
                rowsum[r0 + 8][warp_n] = s[mi][1];
            }
        }
        __syncthreads();
        if (tid < 128) {
            float S = rowsum[tid][0] + rowsum[tid][1] + rowsum[tid][2] + rowsum[tid][3];
            g_s[(size_t)jy * n + rb + tid] = S;
        }
        job = nj;
        jx = njx;
        p ^= 1;
        if (aflip) acur ^= 1;
    }
    if (tid == 0) atomicSub(&g_ctr, cnt);   // self-reset for next replay
}

// ---------------------------------------------------------------------------
// Kernel 3: merge partials -> per-row loss -> scalar (last-block ticket).
// ---------------------------------------------------------------------------
__global__ void finalize_kernel(float* __restrict__ out, int n) {
    int i = blockIdx.x * 256 + threadIdx.x;
    float S = 0.f;
#pragma unroll 16
    for (int sp = 0; sp < JYS; sp++) S += g_s[(size_t)sp * n + i];
    float li = g_diag[i] - (TAU_INV + logf(S));

    __shared__ float sm[256];
    __shared__ int tkt;
    sm[threadIdx.x] = li;
    __syncthreads();
    for (int o = 128; o > 0; o >>= 1) {
        if (threadIdx.x < o) sm[threadIdx.x] += sm[threadIdx.x + o];
        __syncthreads();
    }
    if (threadIdx.x == 0) {
        g_part[blockIdx.x] = sm[0];
        __threadfence();
        tkt = atomicAdd(&g_fin, 1);
    }
    __syncthreads();
    if (tkt == (int)gridDim.x - 1 && threadIdx.x < 32) {
        __threadfence();
        float v = (threadIdx.x < (int)gridDim.x) ? g_part[threadIdx.x] : 0.f;
#pragma unroll
        for (int o = 16; o > 0; o >>= 1)
            v += __shfl_down_sync(0xffffffffu, v, o);
        if (threadIdx.x == 0) {
            out[0] = -v / (float)n;
            g_fin = 0;                       // self-reset for next replay
        }
    }
}

// ---------------------------------------------------------------------------
extern "C" void kernel_launch(void* const* d_in, const int* in_sizes, int n_in,
                              void* d_out, int out_size) {
    const float* im = (const float*)d_in[0];
    const float* rec = (const float*)d_in[1];
    const int* labels = (const int*)d_in[2];   // int32 on device (JAX x64 off)
    float* out = (float*)d_out;

    int n = in_sizes[2];

    cudaFuncSetAttribute(gemm_lse_imma,
                         cudaFuncAttributeMaxDynamicSharedMemorySize, SMEM_TOT);
    int dev = 0, sms = 148;
    cudaGetDevice(&dev);
    cudaDeviceGetAttribute(&sms, cudaDevAttrMultiProcessorCount, dev);

    norm_convert_kernel<<<n * 32 / 256, 256>>>(im, rec);       // #1
    gemm_lse_imma<<<2 * sms, 256, SMEM_TOT>>>(labels, n);      // #2
    finalize_kernel<<<n / 256, 256>>>(out, n);                 // #3
}

// round 13
// speedup vs baseline: 16.5426x; 16.5426x over previous
#include <cuda_runtime.h>
#include <math.h>
#include <stdint.h>

#define TAU_INV (1.0f / 0.07f)
#define Nn 8192
#define Dd 256
#define JYS 32                  // column splits (256 cols each)
#define JX 64                   // row tiles (128 rows each)
#define NJOB (JX * JYS)
#define QINV (1.0 / 16129.0)    // 1/127^2
#define K2C ((float)((1.0/0.07) * QINV * 1.4426950408889634))
#define C2C ((float)((1.0/0.07) * 1.4426950408889634))

// ---- scratch (__device__ globals; allocation-free contract) ----
__device__ uint32_t g_Aq[(size_t)Nn * 64];   // int8x4, word-swizzled rows
__device__ uint32_t g_Bq[(size_t)Nn * 64];
__device__ float g_diag[Nn];
__device__ float g_s[(size_t)JYS * Nn];
__device__ float g_part[64];
__device__ int g_ctr;
__device__ int g_fin;

// smem byte offsets (single dynamic allocation) — R10 layout
#define SO_A0   0
#define SO_A1   32768
#define SO_B0   65536
#define SO_B1   81920
#define SO_LBL  98304            // 2 x 256 ints
#define SO_ROW  100352           // 128 x 4 floats
#define SO_JOB  102400
#define SMEM_TOT 102528

// ---------------------------------------------------------------------------
// Kernel 1: fused norms + diag + int8 quantize (row stays in registers).
// One warp per row; butterfly allreduce; swizzled word layout
// p = j ^ (4*(row&7)) -> conflict-free IMMA fragment LDS.
// ---------------------------------------------------------------------------
__global__ void norm_convert_kernel(const float* __restrict__ im,
                                    const float* __restrict__ rec) {
    int row = (blockIdx.x * blockDim.x + threadIdx.x) >> 5;
    int lane = threadIdx.x & 31;
    const float4* a4 = (const float4*)(im + (size_t)row * Dd);
    const float4* b4 = (const float4*)(rec + (size_t)row * Dd);
    float4 xa0 = a4[lane], xa1 = a4[lane + 32];
    float4 xb0 = b4[lane], xb1 = b4[lane + 32];

    float ssi = xa0.x*xa0.x + xa0.y*xa0.y + xa0.z*xa0.z + xa0.w*xa0.w
              + xa1.x*xa1.x + xa1.y*xa1.y + xa1.z*xa1.z + xa1.w*xa1.w;
    float ssr = xb0.x*xb0.x + xb0.y*xb0.y + xb0.z*xb0.z + xb0.w*xb0.w
              + xb1.x*xb1.x + xb1.y*xb1.y + xb1.z*xb1.z + xb1.w*xb1.w;
    float dot = xa0.x*xb0.x + xa0.y*xb0.y + xa0.z*xb0.z + xa0.w*xb0.w
              + xa1.x*xb1.x + xa1.y*xb1.y + xa1.z*xb1.z + xa1.w*xb1.w;
#pragma unroll
    for (int o = 16; o > 0; o >>= 1) {
        ssi += __shfl_xor_sync(0xffffffffu, ssi, o);
        ssr += __shfl_xor_sync(0xffffffffu, ssr, o);
        dot += __shfl_xor_sync(0xffffffffu, dot, o);
    }
    float ii = 1.0f / fmaxf(sqrtf(ssi), 1e-6f);
    float ir = 1.0f / fmaxf(sqrtf(ssr), 1e-6f);
    if (lane == 0) g_diag[row] = dot * ii * ir * TAU_INV;

    float fa = ii * 127.f, fb = ir * 127.f;
    int p0 = lane ^ (4 * (row & 7));
    int p1 = (lane + 32) ^ (4 * (row & 7));
    int q0, q1, q2, q3;
    q0 = __float2int_rn(xa0.x * fa); q1 = __float2int_rn(xa0.y * fa);
    q2 = __float2int_rn(xa0.z * fa); q3 = __float2int_rn(xa0.w * fa);
    g_Aq[row * 64 + p0] = (q0 & 0xFF) | ((q1 & 0xFF) << 8) | ((q2 & 0xFF) << 16) | (q3 << 24);
    q0 = __float2int_rn(xa1.x * fa); q1 = __float2int_rn(xa1.y * fa);
    q2 = __float2int_rn(xa1.z * fa); q3 = __float2int_rn(xa1.w * fa);
    g_Aq[row * 64 + p1] = (q0 & 0xFF) | ((q1 & 0xFF) << 8) | ((q2 & 0xFF) << 16) | (q3 << 24);
    q0 = __float2int_rn(xb0.x * fb); q1 = __float2int_rn(xb0.y * fb);
    q2 = __float2int_rn(xb0.z * fb); q3 = __float2int_rn(xb0.w * fb);
    g_Bq[row * 64 + p0] = (q0 & 0xFF) | ((q1 & 0xFF) << 8) | ((q2 & 0xFF) << 16) | (q3 << 24);
    q0 = __float2int_rn(xb1.x * fb); q1 = __float2int_rn(xb1.y * fb);
    q2 = __float2int_rn(xb1.z * fb); q3 = __float2int_rn(xb1.w * fb);
    g_Bq[row * 64 + p1] = (q0 & 0xFF) | ((q1 & 0xFF) << 8) | ((q2 & 0xFF) << 16) | (q3 << 24);
}

// Kernel 2: reset job counter.
__global__ void init_kernel() { if (threadIdx.x == 0) g_ctr = 0; }

// ---------------------------------------------------------------------------
// Kernel 3: persistent int8 IMMA GEMM + pipelined fused exp-sum epilogue.
// (R10 verbatim: atomic queue, early grab, double-buffered A, t3 prefetch.)
// ---------------------------------------------------------------------------
#define IMMA(c, av, bv) \
    asm volatile("mma.sync.aligned.m16n8k32.row.col.s32.s8.s8.s32 " \
                 "{%0,%1,%2,%3},{%4,%5,%6,%7},{%8,%9},{%0,%1,%2,%3};" \
                 : "+r"((c)[0]), "+r"((c)[1]), "+r"((c)[2]), "+r"((c)[3]) \
                 : "r"((av)[0]), "r"((av)[1]), "r"((av)[2]), "r"((av)[3]), \
                   "r"((bv)[0]), "r"((bv)[1]))
#define WAIT0() asm volatile("cp.async.wait_group 0;")

__device__ __forceinline__ float ex2f(float x) {
    float r;
    asm("ex2.approx.ftz.f32 %0, %1;" : "=f"(r) : "f"(x));
    return r;
}

__device__ __forceinline__ void copyA(char* dst, int rb, int tid) {
#pragma unroll
    for (int i = 0; i < 8; i++) {
        int id = tid + i * 256;
        int row = id >> 4, c = (id & 15) * 16;
        uint32_t d = (uint32_t)__cvta_generic_to_shared(dst + row * 256 + c);
        const char* s = (const char*)g_Aq + (size_t)(rb + row) * 256 + c;
        asm volatile("cp.async.cg.shared.global [%0], [%1], 16;" :: "r"(d), "l"(s));
    }
    asm volatile("cp.async.commit_group;");
}
__device__ __forceinline__ void copyB(char* dst, int jb, int tid) {
#pragma unroll
    for (int i = 0; i < 4; i++) {
        int id = tid + i * 256;
        int row = id >> 4, c = (id & 15) * 16;
        uint32_t d = (uint32_t)__cvta_generic_to_shared(dst + row * 256 + c);
        const char* s = (const char*)g_Bq + (size_t)(jb + row) * 256 + c;
        asm volatile("cp.async.cg.shared.global [%0], [%1], 16;" :: "r"(d), "l"(s));
    }
    asm volatile("cp.async.commit_group;");
}

__device__ __forceinline__ void mma_tile(int acc[4][2][4], const uint32_t* Aw,
                                         const uint32_t* Bw, int warp_m,
                                         int warp_n, int qr, int qc) {
#pragma unroll
    for (int mi = 0; mi < 4; mi++)
#pragma unroll
        for (int ni = 0; ni < 2; ni++)
#pragma unroll
            for (int k = 0; k < 4; k++) acc[mi][ni][k] = 0;
    int swz = 4 * qr;
#pragma unroll
    for (int ks = 0; ks < 8; ks++) {
        int w0 = (8 * ks + qc) ^ swz;
        int w1 = (8 * ks + 4 + qc) ^ swz;
        uint32_t a[4][4];
#pragma unroll
        for (int mi = 0; mi < 4; mi++) {
            int r0 = (warp_m * 64 + mi * 16 + qr) * 64;
            a[mi][0] = Aw[r0 + w0];
            a[mi][1] = Aw[r0 + 512 + w0];
            a[mi][2] = Aw[r0 + w1];
            a[mi][3] = Aw[r0 + 512 + w1];
        }
        uint32_t b[2][2];
#pragma unroll
        for (int ni = 0; ni < 2; ni++) {
            int rn = (warp_n * 16 + ni * 8 + qr) * 64;
            b[ni][0] = Bw[rn + w0];
            b[ni][1] = Bw[rn + w1];
        }
#pragma unroll
        for (int mi = 0; mi < 4; mi++)
#pragma unroll
            for (int ni = 0; ni < 2; ni++)
                IMMA(acc[mi][ni], a[mi], b[ni]);
    }
}

__device__ __forceinline__ void epi_tile(const int acc[4][2][4], int t, int rb,
                                         int jb0, const int* lblS,
                                         const int labR[4][2], float s[4][2],
                                         int warp_m, int warp_n, int qr, int qc) {
    int jb = jb0 + t * 64;
#pragma unroll
    for (int mi = 0; mi < 4; mi++) {
        int gi0 = rb + warp_m * 64 + mi * 16 + qr;
        int gi1 = gi0 + 8;
#pragma unroll
        for (int ni = 0; ni < 2; ni++) {
            int cl0 = warp_n * 16 + ni * 8 + 2 * qc;
            int cl1 = cl0 + 1;
            int lb0 = lblS[t * 64 + cl0], lb1 = lblS[t * 64 + cl1];
            int gj0 = jb + cl0, gj1 = jb + cl1;
            float e0 = ex2f(fmaf((float)acc[mi][ni][0], K2C, -C2C));
            float e1 = ex2f(fmaf((float)acc[mi][ni][1], K2C, -C2C));
            float e2 = ex2f(fmaf((float)acc[mi][ni][2], K2C, -C2C));
            float e3 = ex2f(fmaf((float)acc[mi][ni][3], K2C, -C2C));
            s[mi][0] += (labR[mi][0] != lb0 || gi0 == gj0) ? e0 : 0.f;
            s[mi][0] += (labR[mi][0] != lb1 || gi0 == gj1) ? e1 : 0.f;
            s[mi][1] += (labR[mi][1] != lb0 || gi1 == gj0) ? e2 : 0.f;
            s[mi][1] += (labR[mi][1] != lb1 || gi1 == gj1) ? e3 : 0.f;
        }
    }
}

__global__ void __launch_bounds__(256, 2)
gemm_lse_imma(const int* __restrict__ labels, int n) {
    extern __shared__ __align__(16) char dsm[];
    char* Abuf0 = dsm + SO_A0;
    char* Abuf1 = dsm + SO_A1;
    char* B0 = dsm + SO_B0;
    char* B1 = dsm + SO_B1;
    int* lbl = (int*)(dsm + SO_LBL);                 // [2][256]
    float (*rowsum)[4] = (float (*)[4])(dsm + SO_ROW);
    int* jobs = (int*)(dsm + SO_JOB);                // [0]=first, [1]=next

    int tid = threadIdx.x, lane = tid & 31, wid = tid >> 5;
    int warp_m = wid >> 2, warp_n = wid & 3;
    int qr = lane >> 2, qc = lane & 3;

    int accA[4][2][4], accB[4][2][4];

    if (tid == 0) jobs[0] = atomicAdd(&g_ctr, 1);
    __syncthreads();
    int job = jobs[0];
    int cur = 0;
    if (job < NJOB) {
        int rb = (job >> 5) * 128, jb0 = (job & 31) * 256;
        copyA(Abuf0, rb, tid);
        copyB(B0, jb0, tid);
        lbl[tid] = labels[jb0 + tid];
    }

    while (job < NJOB) {
        int jx = job >> 5, jy = job & 31;
        int rb = jx * 128, jb0 = jy * 256;
        const uint32_t* Aw = (const uint32_t*)(cur ? Abuf1 : Abuf0);
        const int* lblS = lbl + cur * 256;

        int labR[4][2];
#pragma unroll
        for (int mi = 0; mi < 4; mi++) {
            int r = rb + warp_m * 64 + mi * 16 + qr;
            labR[mi][0] = labels[r];
            labR[mi][1] = labels[r + 8];
        }
        float s[4][2] = {{0.f,0.f},{0.f,0.f},{0.f,0.f},{0.f,0.f}};

        // ---- t0
        WAIT0();
        __syncthreads();
        copyB(B1, jb0 + 64, tid);
        mma_tile(accA, Aw, (const uint32_t*)B0, warp_m, warp_n, qr, qc);
        // ---- t1
        WAIT0();
        __syncthreads();
        copyB(B0, jb0 + 128, tid);
        mma_tile(accB, Aw, (const uint32_t*)B1, warp_m, warp_n, qr, qc);
        epi_tile(accA, 0, rb, jb0, lblS, labR, s, warp_m, warp_n, qr, qc);
        // ---- t2 (early grab of next job)
        WAIT0();
        __syncthreads();
        copyB(B1, jb0 + 192, tid);
        if (tid == 0) jobs[1] = atomicAdd(&g_ctr, 1);
        mma_tile(accA, Aw, (const uint32_t*)B0, warp_m, warp_n, qr, qc);
        epi_tile(accB, 1, rb, jb0, lblS, labR, s, warp_m, warp_n, qr, qc);
        // ---- t3 (prefetch next job's A + first B + labels)
        WAIT0();
        __syncthreads();                 // jobs[1], and B0 free (t2 reads done)
        int nj = jobs[1];
        if (nj < NJOB) {
            int nrb = (nj >> 5) * 128, njb = (nj & 31) * 256;
            copyA(cur ? Abuf0 : Abuf1, nrb, tid);
            copyB(B0, njb, tid);
            lbl[(cur ^ 1) * 256 + tid] = labels[njb + tid];
        }
        mma_tile(accB, Aw, (const uint32_t*)B1, warp_m, warp_n, qr, qc);
        epi_tile(accA, 2, rb, jb0, lblS, labR, s, warp_m, warp_n, qr, qc);
        epi_tile(accB, 3, rb, jb0, lblS, labR, s, warp_m, warp_n, qr, qc);

        // ---- flush: qc-quad reduce, per-(row,warp_n) smem slots, row sum
#pragma unroll
        for (int mi = 0; mi < 4; mi++)
#pragma unroll
            for (int h = 0; h < 2; h++) {
                s[mi][h] += __shfl_xor_sync(0xffffffffu, s[mi][h], 1);
                s[mi][h] += __shfl_xor_sync(0xffffffffu, s[mi][h], 2);
            }
        if (qc == 0) {
#pragma unroll
            for (int mi = 0; mi < 4; mi++) {
                int r0 = warp_m * 64 + mi * 16 + qr;
                rowsum[r0][warp_n] = s[mi][0];
                rowsum[r0 + 8][warp_n] = s[mi][1];
            }
        }
        __syncthreads();
        if (tid < 128) {
            float S = rowsum[tid][0] + rowsum[tid][1] + rowsum[tid][2] + rowsum[tid][3];
            g_s[(size_t)jy * n + rb + tid] = S;
        }
        job = nj;
        cur ^= 1;
    }
}

// ---------------------------------------------------------------------------
// Kernel 4: merge partials -> per-row loss -> scalar (last-block ticket).
// ---------------------------------------------------------------------------
__global__ void finalize_kernel(float* __restrict__ out, int n) {
    int i = blockIdx.x * 256 + threadIdx.x;
    float S = 0.f;
#pragma unroll 8
    for (int sp = 0; sp < JYS; sp++) S += g_s[(size_t)sp * n + i];
    float li = g_diag[i] - (TAU_INV + logf(S));

    __shared__ float sm[256];
    __shared__ int tkt;
    sm[threadIdx.x] = li;
    __syncthreads();
    for (int o = 128; o > 0; o >>= 1) {
        if (threadIdx.x < o) sm[threadIdx.x] += sm[threadIdx.x + o];
        __syncthreads();
    }
    if (threadIdx.x == 0) {
        g_part[blockIdx.x] = sm[0];
        __threadfence();
        tkt = atomicAdd(&g_fin, 1);
    }
    __syncthreads();
    if (tkt == (int)gridDim.x - 1 && threadIdx.x < 32) {
        __threadfence();
        float v = (threadIdx.x < (int)gridDim.x) ? g_part[threadIdx.x] : 0.f;
#pragma unroll
        for (int o = 16; o > 0; o >>= 1)
            v += __shfl_down_sync(0xffffffffu, v, o);
        if (threadIdx.x == 0) {
            out[0] = -v / (float)n;
            g_fin = 0;                       // self-reset for next replay
        }
    }
}

// ---------------------------------------------------------------------------
extern "C" void kernel_launch(void* const* d_in, const int* in_sizes, int n_in,
                              void* d_out, int out_size) {
    const float* im = (const float*)d_in[0];
    const float* rec = (const float*)d_in[1];
    const int* labels = (const int*)d_in[2];   // int32 on device (JAX x64 off)
    float* out = (float*)d_out;

    int n = in_sizes[2];

    cudaFuncSetAttribute(gemm_lse_imma,
                         cudaFuncAttributeMaxDynamicSharedMemorySize, SMEM_TOT);
    int dev = 0, sms = 148;
    cudaGetDevice(&dev);
    cudaDeviceGetAttribute(&sms, cudaDevAttrMultiProcessorCount, dev);

    norm_convert_kernel<<<n * 32 / 256, 256>>>(im, rec);       // #1
    init_kernel<<<1, 32>>>();                                  // #2
    gemm_lse_imma<<<2 * sms, 256, SMEM_TOT>>>(labels, n);      // #3
    finalize_kernel<<<n / 256, 256>>>(out, n);                 // #4
}

// round 14
// speedup vs baseline: 16.6471x; 1.0063x over previous
#include <cuda_runtime.h>
#include <math.h>
#include <stdint.h>

#define TAU_INV (1.0f / 0.07f)
#define Nn 8192
#define Dd 256
#define JYS 32                  // column splits (256 cols each)
#define JX 64                   // row tiles (128 rows each)
#define NJOB (JX * JYS)
#define QINV (1.0 / 16129.0)    // 1/127^2
#define K2C ((float)((1.0/0.07) * QINV * 1.4426950408889634))
#define C2C ((float)((1.0/0.07) * 1.4426950408889634))

// ---- scratch (__device__ globals; allocation-free contract) ----
__device__ uint32_t g_Aq[(size_t)Nn * 64];   // int8x4, word-swizzled rows
__device__ uint32_t g_Bq[(size_t)Nn * 64];
__device__ float g_diag[Nn];
__device__ float g_s[(size_t)Nn * JYS];      // TRANSPOSED: [row][jy]
__device__ float g_part[64];
__device__ int g_ctr;
__device__ int g_fin;

// smem byte offsets (single dynamic allocation) — R10 layout
#define SO_A0   0
#define SO_A1   32768
#define SO_B0   65536
#define SO_B1   81920
#define SO_LBL  98304            // 2 x 256 ints
#define SO_ROW  100352           // 128 x 4 floats
#define SO_JOB  102400
#define SMEM_TOT 102528

// ---------------------------------------------------------------------------
// Kernel 1: fused norms + diag + int8 quantize (row stays in registers).
// One warp per row; butterfly allreduce; swizzled word layout
// p = j ^ (4*(row&7)) -> conflict-free IMMA fragment LDS.
// ---------------------------------------------------------------------------
__global__ void norm_convert_kernel(const float* __restrict__ im,
                                    const float* __restrict__ rec) {
    int row = (blockIdx.x * blockDim.x + threadIdx.x) >> 5;
    int lane = threadIdx.x & 31;
    const float4* a4 = (const float4*)(im + (size_t)row * Dd);
    const float4* b4 = (const float4*)(rec + (size_t)row * Dd);
    float4 xa0 = a4[lane], xa1 = a4[lane + 32];
    float4 xb0 = b4[lane], xb1 = b4[lane + 32];

    float ssi = xa0.x*xa0.x + xa0.y*xa0.y + xa0.z*xa0.z + xa0.w*xa0.w
              + xa1.x*xa1.x + xa1.y*xa1.y + xa1.z*xa1.z + xa1.w*xa1.w;
    float ssr = xb0.x*xb0.x + xb0.y*xb0.y + xb0.z*xb0.z + xb0.w*xb0.w
              + xb1.x*xb1.x + xb1.y*xb1.y + xb1.z*xb1.z + xb1.w*xb1.w;
    float dot = xa0.x*xb0.x + xa0.y*xb0.y + xa0.z*xb0.z + xa0.w*xb0.w
              + xa1.x*xb1.x + xa1.y*xb1.y + xa1.z*xb1.z + xa1.w*xb1.w;
#pragma unroll
    for (int o = 16; o > 0; o >>= 1) {
        ssi += __shfl_xor_sync(0xffffffffu, ssi, o);
        ssr += __shfl_xor_sync(0xffffffffu, ssr, o);
        dot += __shfl_xor_sync(0xffffffffu, dot, o);
    }
    float ii = 1.0f / fmaxf(sqrtf(ssi), 1e-6f);
    float ir = 1.0f / fmaxf(sqrtf(ssr), 1e-6f);
    if (lane == 0) g_diag[row] = dot * ii * ir * TAU_INV;

    float fa = ii * 127.f, fb = ir * 127.f;
    int p0 = lane ^ (4 * (row & 7));
    int p1 = (lane + 32) ^ (4 * (row & 7));
    int q0, q1, q2, q3;
    q0 = __float2int_rn(xa0.x * fa); q1 = __float2int_rn(xa0.y * fa);
    q2 = __float2int_rn(xa0.z * fa); q3 = __float2int_rn(xa0.w * fa);
    g_Aq[row * 64 + p0] = (q0 & 0xFF) | ((q1 & 0xFF) << 8) | ((q2 & 0xFF) << 16) | (q3 << 24);
    q0 = __float2int_rn(xa1.x * fa); q1 = __float2int_rn(xa1.y * fa);
    q2 = __float2int_rn(xa1.z * fa); q3 = __float2int_rn(xa1.w * fa);
    g_Aq[row * 64 + p1] = (q0 & 0xFF) | ((q1 & 0xFF) << 8) | ((q2 & 0xFF) << 16) | (q3 << 24);
    q0 = __float2int_rn(xb0.x * fb); q1 = __float2int_rn(xb0.y * fb);
    q2 = __float2int_rn(xb0.z * fb); q3 = __float2int_rn(xb0.w * fb);
    g_Bq[row * 64 + p0] = (q0 & 0xFF) | ((q1 & 0xFF) << 8) | ((q2 & 0xFF) << 16) | (q3 << 24);
    q0 = __float2int_rn(xb1.x * fb); q1 = __float2int_rn(xb1.y * fb);
    q2 = __float2int_rn(xb1.z * fb); q3 = __float2int_rn(xb1.w * fb);
    g_Bq[row * 64 + p1] = (q0 & 0xFF) | ((q1 & 0xFF) << 8) | ((q2 & 0xFF) << 16) | (q3 << 24);
}

// ---------------------------------------------------------------------------
// Kernel 2: persistent int8 IMMA GEMM + pipelined fused exp-sum epilogue.
// (R10 verbatim except the g_s store address; atomic queue, early grab,
//  double-buffered A, t3 prefetch.)
// ---------------------------------------------------------------------------
#define IMMA(c, av, bv) \
    asm volatile("mma.sync.aligned.m16n8k32.row.col.s32.s8.s8.s32 " \
                 "{%0,%1,%2,%3},{%4,%5,%6,%7},{%8,%9},{%0,%1,%2,%3};" \
                 : "+r"((c)[0]), "+r"((c)[1]), "+r"((c)[2]), "+r"((c)[3]) \
                 : "r"((av)[0]), "r"((av)[1]), "r"((av)[2]), "r"((av)[3]), \
                   "r"((bv)[0]), "r"((bv)[1]))
#define WAIT0() asm volatile("cp.async.wait_group 0;")

__device__ __forceinline__ float ex2f(float x) {
    float r;
    asm("ex2.approx.ftz.f32 %0, %1;" : "=f"(r) : "f"(x));
    return r;
}

__device__ __forceinline__ void copyA(char* dst, int rb, int tid) {
#pragma unroll
    for (int i = 0; i < 8; i++) {
        int id = tid + i * 256;
        int row = id >> 4, c = (id & 15) * 16;
        uint32_t d = (uint32_t)__cvta_generic_to_shared(dst + row * 256 + c);
        const char* s = (const char*)g_Aq + (size_t)(rb + row) * 256 + c;
        asm volatile("cp.async.cg.shared.global [%0], [%1], 16;" :: "r"(d), "l"(s));
    }
    asm volatile("cp.async.commit_group;");
}
__device__ __forceinline__ void copyB(char* dst, int jb, int tid) {
#pragma unroll
    for (int i = 0; i < 4; i++) {
        int id = tid + i * 256;
        int row = id >> 4, c = (id & 15) * 16;
        uint32_t d = (uint32_t)__cvta_generic_to_shared(dst + row * 256 + c);
        const char* s = (const char*)g_Bq + (size_t)(jb + row) * 256 + c;
        asm volatile("cp.async.cg.shared.global [%0], [%1], 16;" :: "r"(d), "l"(s));
    }
    asm volatile("cp.async.commit_group;");
}

__device__ __forceinline__ void mma_tile(int acc[4][2][4], const uint32_t* Aw,
                                         const uint32_t* Bw, int warp_m,
                                         int warp_n, int qr, int qc) {
#pragma unroll
    for (int mi = 0; mi < 4; mi++)
#pragma unroll
        for (int ni = 0; ni < 2; ni++)
#pragma unroll
            for (int k = 0; k < 4; k++) acc[mi][ni][k] = 0;
    int swz = 4 * qr;
#pragma unroll
    for (int ks = 0; ks < 8; ks++) {
        int w0 = (8 * ks + qc) ^ swz;
        int w1 = (8 * ks + 4 + qc) ^ swz;
        uint32_t a[4][4];
#pragma unroll
        for (int mi = 0; mi < 4; mi++) {
            int r0 = (warp_m * 64 + mi * 16 + qr) * 64;
            a[mi][0] = Aw[r0 + w0];
            a[mi][1] = Aw[r0 + 512 + w0];
            a[mi][2] = Aw[r0 + w1];
            a[mi][3] = Aw[r0 + 512 + w1];
        }
        uint32_t b[2][2];
#pragma unroll
        for (int ni = 0; ni < 2; ni++) {
            int rn = (warp_n * 16 + ni * 8 + qr) * 64;
            b[ni][0] = Bw[rn + w0];
            b[ni][1] = Bw[rn + w1];
        }
#pragma unroll
        for (int mi = 0; mi < 4; mi++)
#pragma unroll
            for (int ni = 0; ni < 2; ni++)
                IMMA(acc[mi][ni], a[mi], b[ni]);
    }
}

__device__ __forceinline__ void epi_tile(const int acc[4][2][4], int t, int rb,
                                         int jb0, const int* lblS,
                                         const int labR[4][2], float s[4][2],
                                         int warp_m, int warp_n, int qr, int qc) {
    int jb = jb0 + t * 64;
#pragma unroll
    for (int mi = 0; mi < 4; mi++) {
        int gi0 = rb + warp_m * 64 + mi * 16 + qr;
        int gi1 = gi0 + 8;
#pragma unroll
        for (int ni = 0; ni < 2; ni++) {
            int cl0 = warp_n * 16 + ni * 8 + 2 * qc;
            int cl1 = cl0 + 1;
            int lb0 = lblS[t * 64 + cl0], lb1 = lblS[t * 64 + cl1];
            int gj0 = jb + cl0, gj1 = jb + cl1;
            float e0 = ex2f(fmaf((float)acc[mi][ni][0], K2C, -C2C));
            float e1 = ex2f(fmaf((float)acc[mi][ni][1], K2C, -C2C));
            float e2 = ex2f(fmaf((float)acc[mi][ni][2], K2C, -C2C));
            float e3 = ex2f(fmaf((float)acc[mi][ni][3], K2C, -C2C));
            s[mi][0] += (labR[mi][0] != lb0 || gi0 == gj0) ? e0 : 0.f;
            s[mi][0] += (labR[mi][0] != lb1 || gi0 == gj1) ? e1 : 0.f;
            s[mi][1] += (labR[mi][1] != lb0 || gi1 == gj0) ? e2 : 0.f;
            s[mi][1] += (labR[mi][1] != lb1 || gi1 == gj1) ? e3 : 0.f;
        }
    }
}

__global__ void __launch_bounds__(256, 2)
gemm_lse_imma(const int* __restrict__ labels, int n) {
    extern __shared__ __align__(16) char dsm[];
    char* Abuf0 = dsm + SO_A0;
    char* Abuf1 = dsm + SO_A1;
    char* B0 = dsm + SO_B0;
    char* B1 = dsm + SO_B1;
    int* lbl = (int*)(dsm + SO_LBL);                 // [2][256]
    float (*rowsum)[4] = (float (*)[4])(dsm + SO_ROW);
    int* jobs = (int*)(dsm + SO_JOB);                // [0]=first, [1]=next

    int tid = threadIdx.x, lane = tid & 31, wid = tid >> 5;
    int warp_m = wid >> 2, warp_n = wid & 3;
    int qr = lane >> 2, qc = lane & 3;

    int accA[4][2][4], accB[4][2][4];

    if (tid == 0) jobs[0] = atomicAdd(&g_ctr, 1);
    __syncthreads();
    int job = jobs[0];
    int cur = 0;
    if (job < NJOB) {
        int rb = (job >> 5) * 128, jb0 = (job & 31) * 256;
        copyA(Abuf0, rb, tid);
        copyB(B0, jb0, tid);
        lbl[tid] = labels[jb0 + tid];
    }

    while (job < NJOB) {
        int jx = job >> 5, jy = job & 31;
        int rb = jx * 128, jb0 = jy * 256;
        const uint32_t* Aw = (const uint32_t*)(cur ? Abuf1 : Abuf0);
        const int* lblS = lbl + cur * 256;

        int labR[4][2];
#pragma unroll
        for (int mi = 0; mi < 4; mi++) {
            int r = rb + warp_m * 64 + mi * 16 + qr;
            labR[mi][0] = labels[r];
            labR[mi][1] = labels[r + 8];
        }
        float s[4][2] = {{0.f,0.f},{0.f,0.f},{0.f,0.f},{0.f,0.f}};

        // ---- t0
        WAIT0();
        __syncthreads();
        copyB(B1, jb0 + 64, tid);
        mma_tile(accA, Aw, (const uint32_t*)B0, warp_m, warp_n, qr, qc);
        // ---- t1
        WAIT0();
        __syncthreads();
        copyB(B0, jb0 + 128, tid);
        mma_tile(accB, Aw, (const uint32_t*)B1, warp_m, warp_n, qr, qc);
        epi_tile(accA, 0, rb, jb0, lblS, labR, s, warp_m, warp_n, qr, qc);
        // ---- t2 (early grab of next job)
        WAIT0();
        __syncthreads();
        copyB(B1, jb0 + 192, tid);
        if (tid == 0) jobs[1] = atomicAdd(&g_ctr, 1);
        mma_tile(accA, Aw, (const uint32_t*)B0, warp_m, warp_n, qr, qc);
        epi_tile(accB, 1, rb, jb0, lblS, labR, s, warp_m, warp_n, qr, qc);
        // ---- t3 (prefetch next job's A + first B + labels)
        WAIT0();
        __syncthreads();                 // jobs[1], and B0 free (t2 reads done)
        int nj = jobs[1];
        if (nj < NJOB) {
            int nrb = (nj >> 5) * 128, njb = (nj & 31) * 256;
            copyA(cur ? Abuf0 : Abuf1, nrb, tid);
            copyB(B0, njb, tid);
            lbl[(cur ^ 1) * 256 + tid] = labels[njb + tid];
        }
        mma_tile(accB, Aw, (const uint32_t*)B1, warp_m, warp_n, qr, qc);
        epi_tile(accA, 2, rb, jb0, lblS, labR, s, warp_m, warp_n, qr, qc);
        epi_tile(accB, 3, rb, jb0, lblS, labR, s, warp_m, warp_n, qr, qc);

        // ---- flush: qc-quad reduce, per-(row,warp_n) smem slots, row sum
#pragma unroll
        for (int mi = 0; mi < 4; mi++)
#pragma unroll
            for (int h = 0; h < 2; h++) {
                s[mi][h] += __shfl_xor_sync(0xffffffffu, s[mi][h], 1);
                s[mi][h] += __shfl_xor_sync(0xffffffffu, s[mi][h], 2);
            }
        if (qc == 0) {
#pragma unroll
            for (int mi = 0; mi < 4; mi++) {
                int r0 = warp_m * 64 + mi * 16 + qr;
                rowsum[r0][warp_n] = s[mi][0];
                rowsum[r0 + 8][warp_n] = s[mi][1];
            }
        }
        __syncthreads();
        if (tid < 128) {
            float S = rowsum[tid][0] + rowsum[tid][1] + rowsum[tid][2] + rowsum[tid][3];
            g_s[(size_t)(rb + tid) * JYS + jy] = S;   // transposed layout
        }
        job = nj;
        cur ^= 1;
    }
}

// ---------------------------------------------------------------------------
// Kernel 3: merge partials (contiguous float4 reads) -> per-row loss ->
// scalar (last-block ticket). Also resets g_ctr/g_fin for the next replay.
// ---------------------------------------------------------------------------
__global__ void finalize_kernel(float* __restrict__ out, int n) {
    int i = blockIdx.x * 256 + threadIdx.x;
    const float4* p4 = (const float4*)(g_s + (size_t)i * JYS);
    float S = 0.f;
#pragma unroll
    for (int q = 0; q < JYS / 4; q++) {
        float4 v = p4[q];
        S += v.x + v.y + v.z + v.w;
    }
    float li = g_diag[i] - (TAU_INV + logf(S));

    __shared__ float sm[256];
    __shared__ int tkt;
    sm[threadIdx.x] = li;
    __syncthreads();
    for (int o = 128; o > 0; o >>= 1) {
        if (threadIdx.x < o) sm[threadIdx.x] += sm[threadIdx.x + o];
        __syncthreads();
    }
    if (threadIdx.x == 0) {
        g_part[blockIdx.x] = sm[0];
        __threadfence();
        tkt = atomicAdd(&g_fin, 1);
    }
    __syncthreads();
    if (tkt == (int)gridDim.x - 1 && threadIdx.x < 32) {
        __threadfence();
        float v = (threadIdx.x < (int)gridDim.x) ? g_part[threadIdx.x] : 0.f;
#pragma unroll
        for (int o = 16; o > 0; o >>= 1)
            v += __shfl_down_sync(0xffffffffu, v, o);
        if (threadIdx.x == 0) {
            out[0] = -v / (float)n;
            g_fin = 0;                       // self-reset for next replay
            g_ctr = 0;                       // job queue reset (ordering via launch boundary)
        }
    }
}

// ---------------------------------------------------------------------------
extern "C" void kernel_launch(void* const* d_in, const int* in_sizes, int n_in,
                              void* d_out, int out_size) {
    const float* im = (const float*)d_in[0];
    const float* rec = (const float*)d_in[1];
    const int* labels = (const int*)d_in[2];   // int32 on device (JAX x64 off)
    float* out = (float*)d_out;

    int n = in_sizes[2];

    cudaFuncSetAttribute(gemm_lse_imma,
                         cudaFuncAttributeMaxDynamicSharedMemorySize, SMEM_TOT);
    int dev = 0, sms = 148;
    cudaGetDevice(&dev);
    cudaDeviceGetAttribute(&sms, cudaDevAttrMultiProcessorCount, dev);

    norm_convert_kernel<<<n * 32 / 256, 256>>>(im, rec);       // #1
    gemm_lse_imma<<<2 * sms, 256, SMEM_TOT>>>(labels, n);      // #2
    finalize_kernel<<<n / 256, 256>>>(out, n);                 // #3
}